// round 16
// baseline (speedup 1.0000x reference)
#include <cuda_runtime.h>
#include <cuda_fp16.h>
#include <cstdint>

#define NB    4
#define SEQ   2048
#define DIM   1024
#define HEADS 8
#define HD    128
#define MROWS (NB*SEQ)

// Scratch (device globals — no allocation allowed)
__device__ __half g_ekh [(size_t)NB*HEADS*SEQ*HD];     // exp(k), half
__device__ __half g_ekvh[(size_t)NB*HEADS*SEQ*HD];     // exp(k)*v, half
__device__ __half g_afth[(size_t)MROWS*DIM];           // AFT output, half
__device__ __half g_xh  [(size_t)MROWS*DIM];           // x, half
__device__ __half g_wkh [(size_t)DIM*DIM];             // weights [k][n], half
__device__ __half g_wvh [(size_t)DIM*DIM];
__device__ __half g_woh [(size_t)DIM*DIM];
__device__ __half g_ewh [(size_t)HEADS*SEQ*SEQ];       // exp(w_aft), causal-masked, half

// ---------------------------------------------------------------------------
// helpers
// ---------------------------------------------------------------------------
__device__ __forceinline__ void mma_f16(float c[4],
    uint32_t a0, uint32_t a1, uint32_t a2, uint32_t a3,
    uint32_t b0, uint32_t b1)
{
    asm volatile(
        "mma.sync.aligned.m16n8k16.row.col.f32.f16.f16.f32 "
        "{%0,%1,%2,%3}, {%4,%5,%6,%7}, {%8,%9}, {%0,%1,%2,%3};\n"
        : "+f"(c[0]), "+f"(c[1]), "+f"(c[2]), "+f"(c[3])
        : "r"(a0), "r"(a1), "r"(a2), "r"(a3), "r"(b0), "r"(b1));
}

__device__ __forceinline__ void ldsm_x4(uint32_t r[4], uint32_t addr) {
    asm volatile("ldmatrix.sync.aligned.m8n8.x4.shared.b16 {%0,%1,%2,%3}, [%4];\n"
        : "=r"(r[0]), "=r"(r[1]), "=r"(r[2]), "=r"(r[3]) : "r"(addr));
}
__device__ __forceinline__ void ldsm_x4_t(uint32_t r[4], uint32_t addr) {
    asm volatile("ldmatrix.sync.aligned.m8n8.x4.trans.shared.b16 {%0,%1,%2,%3}, [%4];\n"
        : "=r"(r[0]), "=r"(r[1]), "=r"(r[2]), "=r"(r[3]) : "r"(addr));
}

__device__ __forceinline__ uint32_t smem_u32(const void* p) {
    return (uint32_t)__cvta_generic_to_shared(p);
}
// .cg: bypass L1 — tiles are streamed once; keep L1 port for ldmatrix
__device__ __forceinline__ void cp16(uint32_t dst, const void* src) {
    asm volatile("cp.async.cg.shared.global [%0], [%1], 16;\n" :: "r"(dst), "l"(src));
}
__device__ __forceinline__ void cp_commit() {
    asm volatile("cp.async.commit_group;\n");
}
__device__ __forceinline__ void cp_wait0() {
    asm volatile("cp.async.wait_group 0;\n");
}

__device__ __forceinline__ uint32_t pack_h2(float a, float b) {
    __half2 h = __floats2half2_rn(a, b);
    return *reinterpret_cast<uint32_t*>(&h);
}

// ---------------------------------------------------------------------------
// prep: rounds x + 3 weights to fp16 AND builds causal exp(w_aft) fp16 table.
// Triangle-aware: groups beyond the diagonal 64-block are never read -> skip.
// ---------------------------------------------------------------------------
#define X8  ((size_t)MROWS*DIM/8)             // 1048576
#define W8  ((size_t)DIM*DIM/8)               // 131072
#define EW8 ((size_t)HEADS*SEQ*SEQ/8)         // 4194304
#define PREP_GROUPS (X8 + 3*W8 + EW8)
#define PREP_BLOCKS (PREP_GROUPS/256)         // 22016

__global__ __launch_bounds__(256)
void prep_all(const float4* __restrict__ x, const float4* __restrict__ wk,
              const float4* __restrict__ wv, const float4* __restrict__ wo,
              const float4* __restrict__ w_aft)
{
    size_t i = (size_t)blockIdx.x * 256 + threadIdx.x;
    if (i < X8 + 3*W8) {
        const float4* src;
        uint4* dst;
        if (i < X8) {
            src = x + i * 2;
            dst = (uint4*)g_xh + i;
        } else {
            size_t j = i - X8;
            int seg = (int)(j / W8);
            size_t o = j % W8;
            src = (seg == 0 ? wk : (seg == 1 ? wv : wo)) + o * 2;
            dst = (uint4*)(seg == 0 ? g_wkh : (seg == 1 ? g_wvh : g_woh)) + o;
        }
        float4 a = src[0], b = src[1];
        uint4 u;
        u.x = pack_h2(a.x, a.y); u.y = pack_h2(a.z, a.w);
        u.z = pack_h2(b.x, b.y); u.w = pack_h2(b.z, b.w);
        *dst = u;
    } else {
        size_t j = i - X8 - 3*W8;
        const size_t base = j * 8;
        const int s0 = (int)(base & (SEQ - 1));
        const int t  = (int)((base >> 11) & (SEQ - 1));
        const int t0e = ((t >> 6) + 1) << 6;       // end of diagonal 64-block
        if (s0 > t) {
            if (s0 < t0e) {
                uint4 z = {0u, 0u, 0u, 0u};
                ((uint4*)g_ewh)[j] = z;
            }
            return;
        }
        float4 a = w_aft[j * 2], b = w_aft[j * 2 + 1];
        float e[8];
        e[0] = (s0 + 0 <= t) ? __expf(a.x) : 0.f;
        e[1] = (s0 + 1 <= t) ? __expf(a.y) : 0.f;
        e[2] = (s0 + 2 <= t) ? __expf(a.z) : 0.f;
        e[3] = (s0 + 3 <= t) ? __expf(a.w) : 0.f;
        e[4] = (s0 + 4 <= t) ? __expf(b.x) : 0.f;
        e[5] = (s0 + 5 <= t) ? __expf(b.y) : 0.f;
        e[6] = (s0 + 6 <= t) ? __expf(b.z) : 0.f;
        e[7] = (s0 + 7 <= t) ? __expf(b.w) : 0.f;
        uint4 u;
        u.x = pack_h2(e[0], e[1]); u.y = pack_h2(e[2], e[3]);
        u.z = pack_h2(e[4], e[5]); u.w = pack_h2(e[6], e[7]);
        ((uint4*)g_ewh)[j] = u;
    }
}

// ---------------------------------------------------------------------------
// Tiling: BK=64, 2-stage, one barrier per chunk.
// ---------------------------------------------------------------------------
#define A2_ROWB 144            // 64 halfs + 8 pad
#define A2_STGB (64*A2_ROWB)   // 9216
#define B2_ROWB 272            // 128 halfs + 8 pad
#define B2_STGB (64*B2_ROWB)   // 17408
#define O2_ROWB 528            // 256 halfs + 8 pad
#define O2_STGB (64*O2_ROWB)   // 33792

// kv: block 64m x 128n, warps 2(m)x4(n), warp tile 32x32 dual acc
#define KV_BK_OFF (2*A2_STGB)              // 18432
#define KV_BV_OFF (KV_BK_OFF + 2*B2_STGB)  // 53248
#define KV_SMEM   (KV_BV_OFF + 2*B2_STGB)  // 88064

// out: block 64m x 256n, warps 2(m)x4(n), warp tile 32x64
#define OUT_B_OFF (2*A2_STGB)              // 18432
#define OUT_SMEM  (OUT_B_OFF + 2*O2_STGB)  // 86016

// aft2: block 64t x 128d x 2 BATCHES. 4 B-streams (ek0,ev0,ek1,ev1).
#define AK0_OFF (2*A2_STGB)                // 18432
#define AV0_OFF (AK0_OFF + 2*B2_STGB)      // 53248
#define AK1_OFF (AV0_OFF + 2*B2_STGB)      // 88064
#define AV1_OFF (AK1_OFF + 2*B2_STGB)      // 122880
#define AFT_SMEM (AV1_OFF + 2*B2_STGB)     // 157696 (1 CTA/SM)

// ---------------------------------------------------------------------------
// Fused K+V projection
// ---------------------------------------------------------------------------
__global__ __launch_bounds__(256, 2)
void kv_h(const float* __restrict__ bkb, const float* __restrict__ bvb)
{
    extern __shared__ char smc[];
    const uint32_t sb = smem_u32(smc);

    const int tid  = threadIdx.x;
    const int lane = tid & 31;
    const int warp = tid >> 5;
    const int wm   = warp >> 2;
    const int wn   = warp & 3;
    const int r    = lane >> 2;
    const int cc   = lane & 3;

    const int bm = blockIdx.y << 6;
    const int bn = blockIdx.x << 7;

    const __half* Abase = g_xh  + (size_t)bm * DIM;
    const __half* Kbase = g_wkh + bn;
    const __half* Vbase = g_wvh + bn;

    auto issue = [&](int c) {
        const int st = c & 1;
        const int k0 = c << 6;
        #pragma unroll
        for (int j = 0; j < 2; j++) {
            const int i = tid + (j << 8);
            const int row = i >> 3, g8 = (i & 7) << 3;
            cp16(sb + st * A2_STGB + row * A2_ROWB + g8 * 2,
                 Abase + (size_t)row * DIM + k0 + g8);
        }
        #pragma unroll
        for (int j = 0; j < 4; j++) {
            const int i = tid + (j << 8);
            const int row = i >> 4, g8 = (i & 15) << 3;
            cp16(sb + KV_BK_OFF + st * B2_STGB + row * B2_ROWB + g8 * 2,
                 Kbase + (size_t)(k0 + row) * DIM + g8);
            cp16(sb + KV_BV_OFF + st * B2_STGB + row * B2_ROWB + g8 * 2,
                 Vbase + (size_t)(k0 + row) * DIM + g8);
        }
        cp_commit();
    };

    float acck[2][4][4] = {};
    float accv[2][4][4] = {};

    issue(0);

    const int lrow = lane & 15;
    const int lk8  = (lane >> 4) << 3;

    for (int c = 0; c < 16; c++) {
        cp_wait0();
        __syncthreads();
        if (c + 1 < 16) issue(c + 1);

        const int st = c & 1;
        const uint32_t Abuf = sb + st * A2_STGB;
        const uint32_t Kbuf = sb + KV_BK_OFF + st * B2_STGB;
        const uint32_t Vbuf = sb + KV_BV_OFF + st * B2_STGB;

        #pragma unroll
        for (int ks = 0; ks < 4; ks++) {
            const int k0h = ks << 4;
            uint32_t af[2][4], bfk[2][4], bfv[2][4];
            #pragma unroll
            for (int im = 0; im < 2; im++) {
                const int m0 = (wm << 5) + (im << 4);
                ldsm_x4(af[im], Abuf + (m0 + lrow) * A2_ROWB + (k0h + lk8) * 2);
            }
            #pragma unroll
            for (int ng = 0; ng < 2; ng++) {
                const int n0 = (wn << 5) + (ng << 4);
                ldsm_x4_t(bfk[ng], Kbuf + (k0h + lrow) * B2_ROWB + (n0 + lk8) * 2);
                ldsm_x4_t(bfv[ng], Vbuf + (k0h + lrow) * B2_ROWB + (n0 + lk8) * 2);
            }
            #pragma unroll
            for (int im = 0; im < 2; im++)
                #pragma unroll
                for (int ng = 0; ng < 2; ng++) {
                    mma_f16(acck[im][2*ng],   af[im][0], af[im][1], af[im][2], af[im][3],
                            bfk[ng][0], bfk[ng][1]);
                    mma_f16(acck[im][2*ng+1], af[im][0], af[im][1], af[im][2], af[im][3],
                            bfk[ng][2], bfk[ng][3]);
                    mma_f16(accv[im][2*ng],   af[im][0], af[im][1], af[im][2], af[im][3],
                            bfv[ng][0], bfv[ng][1]);
                    mma_f16(accv[im][2*ng+1], af[im][0], af[im][1], af[im][2], af[im][3],
                            bfv[ng][2], bfv[ng][3]);
                }
        }
    }

    #pragma unroll
    for (int im = 0; im < 2; im++) {
        #pragma unroll
        for (int in = 0; in < 4; in++) {
            #pragma unroll
            for (int e = 0; e < 4; e++) {
                const int row = bm + (wm << 5) + (im << 4) + r + ((e >> 1) << 3);
                const int col = bn + (wn << 5) + (in << 3) + (cc << 1) + (e & 1);
                const float kv = acck[im][in][e] + bkb[col];
                const float vv = accv[im][in][e] + bvb[col];
                const float ek = __expf(kv);
                const int n = row >> 11, s = row & (SEQ - 1);
                const int h = col >> 7, d = col & 127;
                const size_t idx = (((size_t)(n * HEADS + h)) * SEQ + s) * HD + d;
                g_ekh[idx]  = __float2half_rn(ek);
                g_ekvh[idx] = __float2half_rn(ek * vv);
            }
        }
    }
}

// ---------------------------------------------------------------------------
// Output projection: block 64m x 256n, warp tile 32x64.
// ---------------------------------------------------------------------------
__global__ __launch_bounds__(256, 2)
void out_h(const float* __restrict__ bias, float* __restrict__ out)
{
    extern __shared__ char smc[];
    const uint32_t sb = smem_u32(smc);

    const int tid  = threadIdx.x;
    const int lane = tid & 31;
    const int warp = tid >> 5;
    const int wm   = warp >> 2;
    const int wn   = warp & 3;
    const int r    = lane >> 2;
    const int cc   = lane & 3;

    const int bm = blockIdx.y << 6;
    const int bn = blockIdx.x << 8;

    const __half* Abase = g_afth + (size_t)bm * DIM;
    const __half* Wbase = g_woh + bn;

    auto issue = [&](int c) {
        const int st = c & 1;
        const int k0 = c << 6;
        #pragma unroll
        for (int j = 0; j < 2; j++) {
            const int i = tid + (j << 8);
            const int row = i >> 3, g8 = (i & 7) << 3;
            cp16(sb + st * A2_STGB + row * A2_ROWB + g8 * 2,
                 Abase + (size_t)row * DIM + k0 + g8);
        }
        #pragma unroll
        for (int j = 0; j < 8; j++) {
            const int i = tid + (j << 8);
            const int row = i >> 5, g8 = (i & 31) << 3;
            cp16(sb + OUT_B_OFF + st * O2_STGB + row * O2_ROWB + g8 * 2,
                 Wbase + (size_t)(k0 + row) * DIM + g8);
        }
        cp_commit();
    };

    float acc[2][8][4] = {};

    issue(0);

    const int lrow = lane & 15;
    const int lk8  = (lane >> 4) << 3;

    for (int c = 0; c < 16; c++) {
        cp_wait0();
        __syncthreads();
        if (c + 1 < 16) issue(c + 1);

        const int st = c & 1;
        const uint32_t Abuf = sb + st * A2_STGB;
        const uint32_t Bbuf = sb + OUT_B_OFF + st * O2_STGB;

        #pragma unroll
        for (int ks = 0; ks < 4; ks++) {
            const int k0h = ks << 4;
            uint32_t af[2][4], bf[4][4];
            #pragma unroll
            for (int im = 0; im < 2; im++) {
                const int m0 = (wm << 5) + (im << 4);
                ldsm_x4(af[im], Abuf + (m0 + lrow) * A2_ROWB + (k0h + lk8) * 2);
            }
            #pragma unroll
            for (int ng = 0; ng < 4; ng++) {
                const int n0 = (wn << 6) + (ng << 4);
                ldsm_x4_t(bf[ng], Bbuf + (k0h + lrow) * O2_ROWB + (n0 + lk8) * 2);
            }
            #pragma unroll
            for (int im = 0; im < 2; im++)
                #pragma unroll
                for (int ng = 0; ng < 4; ng++) {
                    mma_f16(acc[im][2*ng],   af[im][0], af[im][1], af[im][2], af[im][3],
                            bf[ng][0], bf[ng][1]);
                    mma_f16(acc[im][2*ng+1], af[im][0], af[im][1], af[im][2], af[im][3],
                            bf[ng][2], bf[ng][3]);
                }
        }
    }

    #pragma unroll
    for (int im = 0; im < 2; im++) {
        #pragma unroll
        for (int in = 0; in < 8; in++) {
            #pragma unroll
            for (int e = 0; e < 4; e++) {
                const int row = bm + (wm << 5) + (im << 4) + r + ((e >> 1) << 3);
                const int col = bn + (wn << 6) + (in << 3) + (cc << 1) + (e & 1);
                out[(size_t)row * DIM + col] = acc[im][in][e] + bias[col];
            }
        }
    }
}

// ---------------------------------------------------------------------------
// AFT core, batch-pair: block 64t x 128d x 2 batches (same h -> shared exp(w)
// A-fragments feed both batches' num/den mmas; ratio 10 ldsm : 32 mma).
// s-chunks of 64, 2-stage, one barrier per chunk, heavy-first.
// ---------------------------------------------------------------------------
__global__ __launch_bounds__(256, 1)
void aft_h(int dummy)
{
    extern __shared__ char smc[];
    const uint32_t sb = smem_u32(smc);

    const int tid  = threadIdx.x;
    const int lane = tid & 31;
    const int warp = tid >> 5;
    const int wm   = warp >> 2;
    const int wn   = warp & 3;
    const int r    = lane >> 2;
    const int cc   = lane & 3;

    const int bt = gridDim.x - 1 - blockIdx.x;   // heavy tiles first
    const int t0 = bt << 6;
    const int y  = blockIdx.y;          // 0..15
    const int h  = y >> 1;              // 0..7
    const int n0b = (y & 1) << 1;       // batch pair base: 0 or 2
    const int nh0 = n0b * HEADS + h;
    const int nh1 = (n0b + 1) * HEADS + h;

    const __half* wbase = g_ewh + ((size_t)h * SEQ + t0) * SEQ;
    const __half* ekb[2] = { g_ekh  + (size_t)nh0 * SEQ * HD,
                             g_ekh  + (size_t)nh1 * SEQ * HD };
    const __half* evb[2] = { g_ekvh + (size_t)nh0 * SEQ * HD,
                             g_ekvh + (size_t)nh1 * SEQ * HD };

    const uint32_t kOff[2] = { AK0_OFF, AK1_OFF };
    const uint32_t vOff[2] = { AV0_OFF, AV1_OFF };

    auto issue = [&](int c) {
        const int st = c & 1;
        const int s0 = c << 6;
        #pragma unroll
        for (int j = 0; j < 2; j++) {
            const int i = tid + (j << 8);
            const int row = i >> 3, g8 = (i & 7) << 3;   // row = t-local
            cp16(sb + st * A2_STGB + row * A2_ROWB + g8 * 2,
                 wbase + (size_t)row * SEQ + s0 + g8);
        }
        #pragma unroll
        for (int j = 0; j < 4; j++) {
            const int i = tid + (j << 8);
            const int row = i >> 4, g8 = (i & 15) << 3;  // row = s-local
            #pragma unroll
            for (int b = 0; b < 2; b++) {
                cp16(sb + kOff[b] + st * B2_STGB + row * B2_ROWB + g8 * 2,
                     ekb[b] + (size_t)(s0 + row) * HD + g8);
                cp16(sb + vOff[b] + st * B2_STGB + row * B2_ROWB + g8 * 2,
                     evb[b] + (size_t)(s0 + row) * HD + g8);
            }
        }
        cp_commit();
    };

    float accN[2][2][4][4] = {};   // [batch][im][in][4]
    float accD[2][2][4][4] = {};

    const int nch = bt + 1;    // s-chunks of 64 through diagonal
    issue(0);

    const int lrow = lane & 15;
    const int lk8  = (lane >> 4) << 3;

    for (int c = 0; c < nch; c++) {
        cp_wait0();
        __syncthreads();
        if (c + 1 < nch) issue(c + 1);

        const int st = c & 1;
        const uint32_t Wbuf = sb + st * A2_STGB;

        #pragma unroll
        for (int ks = 0; ks < 4; ks++) {
            const int k0h = ks << 4;
            uint32_t af[2][4];
            #pragma unroll
            for (int im = 0; im < 2; im++) {
                const int m0 = (wm << 5) + (im << 4);
                ldsm_x4(af[im], Wbuf + (m0 + lrow) * A2_ROWB + (k0h + lk8) * 2);
            }
            #pragma unroll
            for (int b = 0; b < 2; b++) {
                const uint32_t Kbuf = sb + kOff[b] + st * B2_STGB;
                const uint32_t Vbuf = sb + vOff[b] + st * B2_STGB;
                uint32_t bk[2][4], bv[2][4];
                #pragma unroll
                for (int ng = 0; ng < 2; ng++) {
                    const int n0 = (wn << 5) + (ng << 4);
                    ldsm_x4_t(bk[ng], Kbuf + (k0h + lrow) * B2_ROWB + (n0 + lk8) * 2);
                    ldsm_x4_t(bv[ng], Vbuf + (k0h + lrow) * B2_ROWB + (n0 + lk8) * 2);
                }
                #pragma unroll
                for (int im = 0; im < 2; im++)
                    #pragma unroll
                    for (int ng = 0; ng < 2; ng++) {
                        mma_f16(accN[b][im][2*ng],   af[im][0], af[im][1], af[im][2], af[im][3],
                                bv[ng][0], bv[ng][1]);
                        mma_f16(accN[b][im][2*ng+1], af[im][0], af[im][1], af[im][2], af[im][3],
                                bv[ng][2], bv[ng][3]);
                        mma_f16(accD[b][im][2*ng],   af[im][0], af[im][1], af[im][2], af[im][3],
                                bk[ng][0], bk[ng][1]);
                        mma_f16(accD[b][im][2*ng+1], af[im][0], af[im][1], af[im][2], af[im][3],
                                bk[ng][2], bk[ng][3]);
                    }
            }
        }
    }

    #pragma unroll
    for (int b = 0; b < 2; b++) {
        const int n = n0b + b;
        #pragma unroll
        for (int im = 0; im < 2; im++) {
            #pragma unroll
            for (int in = 0; in < 4; in++) {
                #pragma unroll
                for (int e = 0; e < 4; e++) {
                    const int t = t0 + (wm << 5) + (im << 4) + r + ((e >> 1) << 3);
                    const int d = (wn << 5) + (in << 3) + (cc << 1) + (e & 1);
                    g_afth[((size_t)(n * SEQ + t)) * DIM + h * HD + d] =
                        __float2half_rn(__fdividef(accN[b][im][in][e], accD[b][im][in][e]));
                }
            }
        }
    }
}

extern "C" void kernel_launch(void* const* d_in, const int* in_sizes, int n_in,
                              void* d_out, int out_size)
{
    const float* x     = (const float*)d_in[0];
    const float* Wk    = (const float*)d_in[1];
    const float* bk    = (const float*)d_in[2];
    const float* Wv    = (const float*)d_in[3];
    const float* bv    = (const float*)d_in[4];
    const float* w_aft = (const float*)d_in[5];
    const float* Wo    = (const float*)d_in[6];
    const float* bo    = (const float*)d_in[7];
    float* out = (float*)d_out;

    cudaFuncSetAttribute(kv_h,  cudaFuncAttributeMaxDynamicSharedMemorySize, KV_SMEM);
    cudaFuncSetAttribute(out_h, cudaFuncAttributeMaxDynamicSharedMemorySize, OUT_SMEM);
    cudaFuncSetAttribute(aft_h, cudaFuncAttributeMaxDynamicSharedMemorySize, AFT_SMEM);

    prep_all<<<PREP_BLOCKS, 256>>>((const float4*)x, (const float4*)Wk,
                                   (const float4*)Wv, (const float4*)Wo,
                                   (const float4*)w_aft);

    kv_h <<<dim3(DIM / 128, MROWS / 64), 256, KV_SMEM>>>(bk, bv);
    aft_h<<<dim3(SEQ / 64, 16), 256, AFT_SMEM>>>(0);
    out_h<<<dim3(DIM / 256, MROWS / 64), 256, OUT_SMEM>>>(bo, out);
}

// round 17
// speedup vs baseline: 1.1217x; 1.1217x over previous
#include <cuda_runtime.h>
#include <cuda_fp16.h>
#include <cstdint>

#define NB    4
#define SEQ   2048
#define DIM   1024
#define HEADS 8
#define HD    128
#define MROWS (NB*SEQ)

// Scratch (device globals — no allocation allowed)
__device__ __half g_ekh [(size_t)NB*HEADS*SEQ*HD];     // exp(k), half
__device__ __half g_ekvh[(size_t)NB*HEADS*SEQ*HD];     // exp(k)*v, half
__device__ __half g_afth[(size_t)MROWS*DIM];           // AFT output, half
__device__ __half g_xh  [(size_t)MROWS*DIM];           // x, half
__device__ __half g_wkh [(size_t)DIM*DIM];             // weights [k][n], half
__device__ __half g_wvh [(size_t)DIM*DIM];
__device__ __half g_woh [(size_t)DIM*DIM];
__device__ __half g_ewh [(size_t)HEADS*SEQ*SEQ];       // exp(w_aft), causal-masked, half

// ---------------------------------------------------------------------------
// helpers
// ---------------------------------------------------------------------------
__device__ __forceinline__ void mma_f16(float c[4],
    uint32_t a0, uint32_t a1, uint32_t a2, uint32_t a3,
    uint32_t b0, uint32_t b1)
{
    asm volatile(
        "mma.sync.aligned.m16n8k16.row.col.f32.f16.f16.f32 "
        "{%0,%1,%2,%3}, {%4,%5,%6,%7}, {%8,%9}, {%0,%1,%2,%3};\n"
        : "+f"(c[0]), "+f"(c[1]), "+f"(c[2]), "+f"(c[3])
        : "r"(a0), "r"(a1), "r"(a2), "r"(a3), "r"(b0), "r"(b1));
}

__device__ __forceinline__ void ldsm_x4(uint32_t r[4], uint32_t addr) {
    asm volatile("ldmatrix.sync.aligned.m8n8.x4.shared.b16 {%0,%1,%2,%3}, [%4];\n"
        : "=r"(r[0]), "=r"(r[1]), "=r"(r[2]), "=r"(r[3]) : "r"(addr));
}
__device__ __forceinline__ void ldsm_x4_t(uint32_t r[4], uint32_t addr) {
    asm volatile("ldmatrix.sync.aligned.m8n8.x4.trans.shared.b16 {%0,%1,%2,%3}, [%4];\n"
        : "=r"(r[0]), "=r"(r[1]), "=r"(r[2]), "=r"(r[3]) : "r"(addr));
}

__device__ __forceinline__ uint32_t smem_u32(const void* p) {
    return (uint32_t)__cvta_generic_to_shared(p);
}
// .cg: bypass L1 — tiles are streamed once; keep L1 port for ldmatrix
__device__ __forceinline__ void cp16(uint32_t dst, const void* src) {
    asm volatile("cp.async.cg.shared.global [%0], [%1], 16;\n" :: "r"(dst), "l"(src));
}
__device__ __forceinline__ void cp_commit() {
    asm volatile("cp.async.commit_group;\n");
}
__device__ __forceinline__ void cp_wait0() {
    asm volatile("cp.async.wait_group 0;\n");
}

__device__ __forceinline__ uint32_t pack_h2(float a, float b) {
    __half2 h = __floats2half2_rn(a, b);
    return *reinterpret_cast<uint32_t*>(&h);
}

// ---------------------------------------------------------------------------
// prep: rounds x + 3 weights to fp16 AND builds causal exp(w_aft) fp16 table.
// Triangle-aware: groups beyond the diagonal 64-block are never read -> skip.
// ---------------------------------------------------------------------------
#define X8  ((size_t)MROWS*DIM/8)             // 1048576
#define W8  ((size_t)DIM*DIM/8)               // 131072
#define EW8 ((size_t)HEADS*SEQ*SEQ/8)         // 4194304
#define PREP_GROUPS (X8 + 3*W8 + EW8)
#define PREP_BLOCKS (PREP_GROUPS/256)         // 22016

__global__ __launch_bounds__(256)
void prep_all(const float4* __restrict__ x, const float4* __restrict__ wk,
              const float4* __restrict__ wv, const float4* __restrict__ wo,
              const float4* __restrict__ w_aft)
{
    size_t i = (size_t)blockIdx.x * 256 + threadIdx.x;
    if (i < X8 + 3*W8) {
        const float4* src;
        uint4* dst;
        if (i < X8) {
            src = x + i * 2;
            dst = (uint4*)g_xh + i;
        } else {
            size_t j = i - X8;
            int seg = (int)(j / W8);
            size_t o = j % W8;
            src = (seg == 0 ? wk : (seg == 1 ? wv : wo)) + o * 2;
            dst = (uint4*)(seg == 0 ? g_wkh : (seg == 1 ? g_wvh : g_woh)) + o;
        }
        float4 a = src[0], b = src[1];
        uint4 u;
        u.x = pack_h2(a.x, a.y); u.y = pack_h2(a.z, a.w);
        u.z = pack_h2(b.x, b.y); u.w = pack_h2(b.z, b.w);
        *dst = u;
    } else {
        size_t j = i - X8 - 3*W8;
        const size_t base = j * 8;
        const int s0 = (int)(base & (SEQ - 1));
        const int t  = (int)((base >> 11) & (SEQ - 1));
        const int t0e = ((t >> 6) + 1) << 6;       // end of diagonal 64-block
        if (s0 > t) {
            if (s0 < t0e) {
                uint4 z = {0u, 0u, 0u, 0u};
                ((uint4*)g_ewh)[j] = z;
            }
            return;
        }
        float4 a = w_aft[j * 2], b = w_aft[j * 2 + 1];
        float e[8];
        e[0] = (s0 + 0 <= t) ? __expf(a.x) : 0.f;
        e[1] = (s0 + 1 <= t) ? __expf(a.y) : 0.f;
        e[2] = (s0 + 2 <= t) ? __expf(a.z) : 0.f;
        e[3] = (s0 + 3 <= t) ? __expf(a.w) : 0.f;
        e[4] = (s0 + 4 <= t) ? __expf(b.x) : 0.f;
        e[5] = (s0 + 5 <= t) ? __expf(b.y) : 0.f;
        e[6] = (s0 + 6 <= t) ? __expf(b.z) : 0.f;
        e[7] = (s0 + 7 <= t) ? __expf(b.w) : 0.f;
        uint4 u;
        u.x = pack_h2(e[0], e[1]); u.y = pack_h2(e[2], e[3]);
        u.z = pack_h2(e[4], e[5]); u.w = pack_h2(e[6], e[7]);
        ((uint4*)g_ewh)[j] = u;
    }
}

// ---------------------------------------------------------------------------
// Tiling: BK=64, 2-stage, one barrier per chunk.
// ---------------------------------------------------------------------------
#define A2_ROWB 144            // 64 halfs + 8 pad
#define A2_STGB (64*A2_ROWB)   // 9216
#define B2_ROWB 272            // 128 halfs + 8 pad
#define B2_STGB (64*B2_ROWB)   // 17408

// kv: block 64m x 128n, warps 2(m)x4(n), warp tile 32x32 dual acc
#define KV_BK_OFF (2*A2_STGB)              // 18432
#define KV_BV_OFF (KV_BK_OFF + 2*B2_STGB)  // 53248
#define KV_SMEM   (KV_BV_OFF + 2*B2_STGB)  // 88064

// out: block 64m x 128n, warps 2(m)x4(n), warp tile 32x32 single acc, 3 CTA/SM
#define OUT_B_OFF (2*A2_STGB)              // 18432
#define OUT_SMEM  (OUT_B_OFF + 2*B2_STGB)  // 53248

// aft: block 64t x 128d, warps 2(t)x4(d), warp tile 32x32 dual acc
#define AE_OFF  (2*A2_STGB)                // 18432
#define AV_OFF  (AE_OFF + 2*B2_STGB)       // 53248
#define AFT_SMEM (AV_OFF + 2*B2_STGB)      // 88064

// ---------------------------------------------------------------------------
// Fused K+V projection
// ---------------------------------------------------------------------------
__global__ __launch_bounds__(256, 2)
void kv_h(const float* __restrict__ bkb, const float* __restrict__ bvb)
{
    extern __shared__ char smc[];
    const uint32_t sb = smem_u32(smc);

    const int tid  = threadIdx.x;
    const int lane = tid & 31;
    const int warp = tid >> 5;
    const int wm   = warp >> 2;
    const int wn   = warp & 3;
    const int r    = lane >> 2;
    const int cc   = lane & 3;

    const int bm = blockIdx.y << 6;
    const int bn = blockIdx.x << 7;

    const __half* Abase = g_xh  + (size_t)bm * DIM;
    const __half* Kbase = g_wkh + bn;
    const __half* Vbase = g_wvh + bn;

    auto issue = [&](int c) {
        const int st = c & 1;
        const int k0 = c << 6;
        #pragma unroll
        for (int j = 0; j < 2; j++) {
            const int i = tid + (j << 8);
            const int row = i >> 3, g8 = (i & 7) << 3;
            cp16(sb + st * A2_STGB + row * A2_ROWB + g8 * 2,
                 Abase + (size_t)row * DIM + k0 + g8);
        }
        #pragma unroll
        for (int j = 0; j < 4; j++) {
            const int i = tid + (j << 8);
            const int row = i >> 4, g8 = (i & 15) << 3;
            cp16(sb + KV_BK_OFF + st * B2_STGB + row * B2_ROWB + g8 * 2,
                 Kbase + (size_t)(k0 + row) * DIM + g8);
            cp16(sb + KV_BV_OFF + st * B2_STGB + row * B2_ROWB + g8 * 2,
                 Vbase + (size_t)(k0 + row) * DIM + g8);
        }
        cp_commit();
    };

    float acck[2][4][4] = {};
    float accv[2][4][4] = {};

    issue(0);

    const int lrow = lane & 15;
    const int lk8  = (lane >> 4) << 3;

    for (int c = 0; c < 16; c++) {
        cp_wait0();
        __syncthreads();
        if (c + 1 < 16) issue(c + 1);

        const int st = c & 1;
        const uint32_t Abuf = sb + st * A2_STGB;
        const uint32_t Kbuf = sb + KV_BK_OFF + st * B2_STGB;
        const uint32_t Vbuf = sb + KV_BV_OFF + st * B2_STGB;

        #pragma unroll
        for (int ks = 0; ks < 4; ks++) {
            const int k0h = ks << 4;
            uint32_t af[2][4], bfk[2][4], bfv[2][4];
            #pragma unroll
            for (int im = 0; im < 2; im++) {
                const int m0 = (wm << 5) + (im << 4);
                ldsm_x4(af[im], Abuf + (m0 + lrow) * A2_ROWB + (k0h + lk8) * 2);
            }
            #pragma unroll
            for (int ng = 0; ng < 2; ng++) {
                const int n0 = (wn << 5) + (ng << 4);
                ldsm_x4_t(bfk[ng], Kbuf + (k0h + lrow) * B2_ROWB + (n0 + lk8) * 2);
                ldsm_x4_t(bfv[ng], Vbuf + (k0h + lrow) * B2_ROWB + (n0 + lk8) * 2);
            }
            #pragma unroll
            for (int im = 0; im < 2; im++)
                #pragma unroll
                for (int ng = 0; ng < 2; ng++) {
                    mma_f16(acck[im][2*ng],   af[im][0], af[im][1], af[im][2], af[im][3],
                            bfk[ng][0], bfk[ng][1]);
                    mma_f16(acck[im][2*ng+1], af[im][0], af[im][1], af[im][2], af[im][3],
                            bfk[ng][2], bfk[ng][3]);
                    mma_f16(accv[im][2*ng],   af[im][0], af[im][1], af[im][2], af[im][3],
                            bfv[ng][0], bfv[ng][1]);
                    mma_f16(accv[im][2*ng+1], af[im][0], af[im][1], af[im][2], af[im][3],
                            bfv[ng][2], bfv[ng][3]);
                }
        }
    }

    #pragma unroll
    for (int im = 0; im < 2; im++) {
        #pragma unroll
        for (int in = 0; in < 4; in++) {
            #pragma unroll
            for (int e = 0; e < 4; e++) {
                const int row = bm + (wm << 5) + (im << 4) + r + ((e >> 1) << 3);
                const int col = bn + (wn << 5) + (in << 3) + (cc << 1) + (e & 1);
                const float kv = acck[im][in][e] + bkb[col];
                const float vv = accv[im][in][e] + bvb[col];
                const float ek = __expf(kv);
                const int n = row >> 11, s = row & (SEQ - 1);
                const int h = col >> 7, d = col & 127;
                const size_t idx = (((size_t)(n * HEADS + h)) * SEQ + s) * HD + d;
                g_ekh[idx]  = __float2half_rn(ek);
                g_ekvh[idx] = __float2half_rn(ek * vv);
            }
        }
    }
}

// ---------------------------------------------------------------------------
// Output projection: block 64m x 128n, warp tile 32x32 single acc.
// 53 KB smem + ~80 regs -> 3 CTAs/SM for cross-CTA latency overlap.
// ---------------------------------------------------------------------------
__global__ __launch_bounds__(256, 3)
void out_h(const float* __restrict__ bias, float* __restrict__ out)
{
    extern __shared__ char smc[];
    const uint32_t sb = smem_u32(smc);

    const int tid  = threadIdx.x;
    const int lane = tid & 31;
    const int warp = tid >> 5;
    const int wm   = warp >> 2;
    const int wn   = warp & 3;
    const int r    = lane >> 2;
    const int cc   = lane & 3;

    const int bm = blockIdx.y << 6;
    const int bn = blockIdx.x << 7;

    const __half* Abase = g_afth + (size_t)bm * DIM;
    const __half* Wbase = g_woh + bn;

    auto issue = [&](int c) {
        const int st = c & 1;
        const int k0 = c << 6;
        #pragma unroll
        for (int j = 0; j < 2; j++) {
            const int i = tid + (j << 8);
            const int row = i >> 3, g8 = (i & 7) << 3;
            cp16(sb + st * A2_STGB + row * A2_ROWB + g8 * 2,
                 Abase + (size_t)row * DIM + k0 + g8);
        }
        #pragma unroll
        for (int j = 0; j < 4; j++) {
            const int i = tid + (j << 8);
            const int row = i >> 4, g8 = (i & 15) << 3;
            cp16(sb + OUT_B_OFF + st * B2_STGB + row * B2_ROWB + g8 * 2,
                 Wbase + (size_t)(k0 + row) * DIM + g8);
        }
        cp_commit();
    };

    float acc[2][4][4] = {};

    issue(0);

    const int lrow = lane & 15;
    const int lk8  = (lane >> 4) << 3;

    for (int c = 0; c < 16; c++) {
        cp_wait0();
        __syncthreads();
        if (c + 1 < 16) issue(c + 1);

        const int st = c & 1;
        const uint32_t Abuf = sb + st * A2_STGB;
        const uint32_t Bbuf = sb + OUT_B_OFF + st * B2_STGB;

        #pragma unroll
        for (int ks = 0; ks < 4; ks++) {
            const int k0h = ks << 4;
            uint32_t af[2][4], bf[2][4];
            #pragma unroll
            for (int im = 0; im < 2; im++) {
                const int m0 = (wm << 5) + (im << 4);
                ldsm_x4(af[im], Abuf + (m0 + lrow) * A2_ROWB + (k0h + lk8) * 2);
            }
            #pragma unroll
            for (int ng = 0; ng < 2; ng++) {
                const int n0 = (wn << 5) + (ng << 4);
                ldsm_x4_t(bf[ng], Bbuf + (k0h + lrow) * B2_ROWB + (n0 + lk8) * 2);
            }
            #pragma unroll
            for (int im = 0; im < 2; im++)
                #pragma unroll
                for (int ng = 0; ng < 2; ng++) {
                    mma_f16(acc[im][2*ng],   af[im][0], af[im][1], af[im][2], af[im][3],
                            bf[ng][0], bf[ng][1]);
                    mma_f16(acc[im][2*ng+1], af[im][0], af[im][1], af[im][2], af[im][3],
                            bf[ng][2], bf[ng][3]);
                }
        }
    }

    #pragma unroll
    for (int im = 0; im < 2; im++) {
        #pragma unroll
        for (int in = 0; in < 4; in++) {
            #pragma unroll
            for (int e = 0; e < 4; e++) {
                const int row = bm + (wm << 5) + (im << 4) + r + ((e >> 1) << 3);
                const int col = bn + (wn << 5) + (in << 3) + (cc << 1) + (e & 1);
                out[(size_t)row * DIM + col] = acc[im][in][e] + bias[col];
            }
        }
    }
}

// ---------------------------------------------------------------------------
// AFT core: block 64t x 128d, warps 2(t)x4(d), warp tile 32x32 dual-acc.
// s-chunks of 64, 2-stage, one barrier per chunk, heavy-first. (round-15)
// ---------------------------------------------------------------------------
__global__ __launch_bounds__(256, 2)
void aft_h(int dummy)
{
    extern __shared__ char smc[];
    const uint32_t sb = smem_u32(smc);

    const int tid  = threadIdx.x;
    const int lane = tid & 31;
    const int warp = tid >> 5;
    const int wm   = warp >> 2;
    const int wn   = warp & 3;
    const int r    = lane >> 2;
    const int cc   = lane & 3;

    const int bt = gridDim.x - 1 - blockIdx.x;   // heavy tiles first
    const int t0 = bt << 6;
    const int nh = blockIdx.y;
    const int n  = nh >> 3;
    const int h  = nh & 7;

    const __half* wbase  = g_ewh  + ((size_t)h * SEQ + t0) * SEQ;
    const __half* ekbase = g_ekh  + (size_t)nh * SEQ * HD;
    const __half* evbase = g_ekvh + (size_t)nh * SEQ * HD;

    auto issue = [&](int c) {
        const int st = c & 1;
        const int s0 = c << 6;
        #pragma unroll
        for (int j = 0; j < 2; j++) {
            const int i = tid + (j << 8);
            const int row = i >> 3, g8 = (i & 7) << 3;   // row = t-local
            cp16(sb + st * A2_STGB + row * A2_ROWB + g8 * 2,
                 wbase + (size_t)row * SEQ + s0 + g8);
        }
        #pragma unroll
        for (int j = 0; j < 4; j++) {
            const int i = tid + (j << 8);
            const int row = i >> 4, g8 = (i & 15) << 3;  // row = s-local
            cp16(sb + AE_OFF + st * B2_STGB + row * B2_ROWB + g8 * 2,
                 ekbase + (size_t)(s0 + row) * HD + g8);
            cp16(sb + AV_OFF + st * B2_STGB + row * B2_ROWB + g8 * 2,
                 evbase + (size_t)(s0 + row) * HD + g8);
        }
        cp_commit();
    };

    float accN[2][4][4] = {};
    float accD[2][4][4] = {};

    const int nch = bt + 1;    // s-chunks of 64 through diagonal
    issue(0);

    const int lrow = lane & 15;
    const int lk8  = (lane >> 4) << 3;

    for (int c = 0; c < nch; c++) {
        cp_wait0();
        __syncthreads();
        if (c + 1 < nch) issue(c + 1);

        const int st = c & 1;
        const uint32_t Wbuf = sb + st * A2_STGB;
        const uint32_t Kbuf = sb + AE_OFF + st * B2_STGB;
        const uint32_t Vbuf = sb + AV_OFF + st * B2_STGB;

        #pragma unroll
        for (int ks = 0; ks < 4; ks++) {
            const int k0h = ks << 4;
            uint32_t af[2][4], bk[2][4], bv[2][4];
            #pragma unroll
            for (int im = 0; im < 2; im++) {
                const int m0 = (wm << 5) + (im << 4);
                ldsm_x4(af[im], Wbuf + (m0 + lrow) * A2_ROWB + (k0h + lk8) * 2);
            }
            #pragma unroll
            for (int ng = 0; ng < 2; ng++) {
                const int n0 = (wn << 5) + (ng << 4);
                ldsm_x4_t(bk[ng], Kbuf + (k0h + lrow) * B2_ROWB + (n0 + lk8) * 2);
                ldsm_x4_t(bv[ng], Vbuf + (k0h + lrow) * B2_ROWB + (n0 + lk8) * 2);
            }
            #pragma unroll
            for (int im = 0; im < 2; im++)
                #pragma unroll
                for (int ng = 0; ng < 2; ng++) {
                    mma_f16(accN[im][2*ng],   af[im][0], af[im][1], af[im][2], af[im][3],
                            bv[ng][0], bv[ng][1]);
                    mma_f16(accN[im][2*ng+1], af[im][0], af[im][1], af[im][2], af[im][3],
                            bv[ng][2], bv[ng][3]);
                    mma_f16(accD[im][2*ng],   af[im][0], af[im][1], af[im][2], af[im][3],
                            bk[ng][0], bk[ng][1]);
                    mma_f16(accD[im][2*ng+1], af[im][0], af[im][1], af[im][2], af[im][3],
                            bk[ng][2], bk[ng][3]);
                }
        }
    }

    #pragma unroll
    for (int im = 0; im < 2; im++) {
        #pragma unroll
        for (int in = 0; in < 4; in++) {
            #pragma unroll
            for (int e = 0; e < 4; e++) {
                const int t = t0 + (wm << 5) + (im << 4) + r + ((e >> 1) << 3);
                const int d = (wn << 5) + (in << 3) + (cc << 1) + (e & 1);
                g_afth[((size_t)(n * SEQ + t)) * DIM + h * HD + d] =
                    __float2half_rn(__fdividef(accN[im][in][e], accD[im][in][e]));
            }
        }
    }
}

extern "C" void kernel_launch(void* const* d_in, const int* in_sizes, int n_in,
                              void* d_out, int out_size)
{
    const float* x     = (const float*)d_in[0];
    const float* Wk    = (const float*)d_in[1];
    const float* bk    = (const float*)d_in[2];
    const float* Wv    = (const float*)d_in[3];
    const float* bv    = (const float*)d_in[4];
    const float* w_aft = (const float*)d_in[5];
    const float* Wo    = (const float*)d_in[6];
    const float* bo    = (const float*)d_in[7];
    float* out = (float*)d_out;

    cudaFuncSetAttribute(kv_h,  cudaFuncAttributeMaxDynamicSharedMemorySize, KV_SMEM);
    cudaFuncSetAttribute(out_h, cudaFuncAttributeMaxDynamicSharedMemorySize, OUT_SMEM);
    cudaFuncSetAttribute(aft_h, cudaFuncAttributeMaxDynamicSharedMemorySize, AFT_SMEM);

    prep_all<<<PREP_BLOCKS, 256>>>((const float4*)x, (const float4*)Wk,
                                   (const float4*)Wv, (const float4*)Wo,
                                   (const float4*)w_aft);

    kv_h <<<dim3(DIM / 128, MROWS / 64), 256, KV_SMEM>>>(bk, bv);
    aft_h<<<dim3(SEQ / 64, NB * HEADS), 256, AFT_SMEM>>>(0);
    out_h<<<dim3(DIM / 128, MROWS / 64), 256, OUT_SMEM>>>(bo, out);
}